// round 10
// baseline (speedup 1.0000x reference)
#include <cuda_runtime.h>
#include <cstdint>

// GrokkingSNN: B=32768, hidden=512, p=97, 15 steps.
//   cur1[b,j] = P1[x0,j] + P2[x1,j] + b1[j], P = E @ W1half.T
//   9409 distinct pairs -> simulate per pair; mem2 = S @ W2.T + b2*G.
// R10: precompute reverted to single-chain accumulators (bit-identical P,
//      restores rel_err margin) with 4 v-rows/thread to halve w-LDS traffic.
//      Pair kernel identical to R9 (per-element identical to R8).

#define HIDDEN 512
#define PDIM 97
#define NPAIR (PDIM * PDIM)   // 9409
#define NSTEPS 15
#define UPITCH 104

#define NP 32       // pairs per CTA (pair kernel)
#define SHP 260     // S bf16x2 pitch (u32/row)
#define WHP 36      // W2 bf16x2 chunk pitch (u32/row)
#define KCH 64      // K per W2 chunk
#define WCHUNK (104 * WHP)

// precompute tiling
#define PJT 32      // j per block
#define PVT 16      // v per block (4 per thread)
#define W1P4 33     // W1 chunk pitch in float4

__device__ float g_P[2 * PDIM * HIDDEN];
__device__ float g_U[NPAIR * UPITCH];

typedef unsigned long long ull;
typedef unsigned int u32;

__device__ __forceinline__ ull fma2v(ull a, ull b, ull c) {
    ull d; asm("fma.rn.f32x2 %0, %1, %2, %3;" : "=l"(d) : "l"(a), "l"(b), "l"(c));
    return d;
}
__device__ __forceinline__ ull add2(ull a, ull b) {
    ull d; asm("add.rn.f32x2 %0, %1, %2;" : "=l"(d) : "l"(a), "l"(b));
    return d;
}
__device__ __forceinline__ ull pack2(float lo, float hi) {
    ull u; asm("mov.b64 %0, {%1, %2};" : "=l"(u) : "f"(lo), "f"(hi));
    return u;
}
__device__ __forceinline__ ull dup_f32(float w) {
    ull u; asm("mov.b64 %0, {%1, %1};" : "=l"(u) : "f"(w));
    return u;
}
__device__ __forceinline__ void unpack2(ull v, float& lo, float& hi) {
    asm("mov.b64 {%0, %1}, %2;" : "=f"(lo), "=f"(hi) : "l"(v));
}
__device__ __forceinline__ float fsetgt(float a, float b) {
    float d; asm("set.gt.f32.f32 %0, %1, %2;" : "=f"(d) : "f"(a), "f"(b));
    return d;
}
__device__ __forceinline__ u32 bfpack(float hif, float lof) {
    u32 d; asm("cvt.rn.bf16x2.f32 %0, %1, %2;" : "=r"(d) : "f"(hif), "f"(lof));
    return d;
}
__device__ __forceinline__ float bflo(u32 d) { return __uint_as_float(d << 16); }
__device__ __forceinline__ float bfhi(u32 d) { return __uint_as_float(d & 0xFFFF0000u); }

__device__ __forceinline__ void mma_bf16(float* c, const u32* a, u32 b0, u32 b1) {
    asm("mma.sync.aligned.m16n8k16.row.col.f32.bf16.bf16.f32 "
        "{%0,%1,%2,%3}, {%4,%5,%6,%7}, {%8,%9}, {%0,%1,%2,%3};"
        : "+f"(c[0]), "+f"(c[1]), "+f"(c[2]), "+f"(c[3])
        : "r"(a[0]), "r"(a[1]), "r"(a[2]), "r"(a[3]), "r"(b0), "r"(b1));
}

// ---------------------------------------------------------------------------
// Kernel A: P[s][v][j] = sum_k E[v][k] * W1[j][s*512+k]
// grid (16 jt, 7 vt of 16 v, 2 s) = 224 CTAs, 128 threads.
// Thread = (j lane, 4 v rows). Each v-row: ONE k-ascending FMA chain
// (bit-identical to R8). w LDS.128 amortized over 4 rows.
// ---------------------------------------------------------------------------
__global__ void __launch_bounds__(128) precompute_kernel(
    const float* __restrict__ E, const float* __restrict__ W1)
{
    extern __shared__ float4 psm[];
    float4* Es4  = psm;                        // [PVT][128]
    float4* W1s4 = psm + PVT * (HIDDEN / 4);   // [PJT][W1P4]

    const int jt = blockIdx.x, vt = blockIdx.y, s = blockIdx.z;
    const int tid  = threadIdx.x;
    const int lane = tid & 31;    // j within tile
    const int grp  = tid >> 5;    // warp -> 4 v rows
    const int vbase = vt * PVT;

    // stage E tile (coalesced, zero-fill past row 96)
    const float4* E4 = reinterpret_cast<const float4*>(E);
    const float4 z4 = make_float4(0.f, 0.f, 0.f, 0.f);
#pragma unroll
    for (int r = 0; r < PVT * (HIDDEN / 4) / 128; r++) {
        int idx = tid + 128 * r;
        int vv = idx >> 7;
        int c4 = idx & 127;
        int v  = vbase + vv;
        Es4[vv * 128 + c4] = (v < PDIM) ? __ldg(E4 + v * 128 + c4) : z4;
    }

    // W1 row stride = 256 float4; chunk = [32 j][32 float4]
    const float4* W14 = reinterpret_cast<const float4*>(W1);
    const int srow = tid >> 5;
    const int sc4  = tid & 31;

    float4 r[8];
#pragma unroll
    for (int i = 0; i < 8; i++)
        r[i] = __ldg(W14 + (size_t)(jt * PJT + srow + 4 * i) * 256 + s * 128 + sc4);

    float acc[4];
#pragma unroll
    for (int u = 0; u < 4; u++) acc[u] = 0.f;

    for (int kb = 0; kb < 4; kb++) {
#pragma unroll
        for (int i = 0; i < 8; i++)
            W1s4[(srow + 4 * i) * W1P4 + sc4] = r[i];
        __syncthreads();
        if (kb < 3) {
#pragma unroll
            for (int i = 0; i < 8; i++)
                r[i] = __ldg(W14 + (size_t)(jt * PJT + srow + 4 * i) * 256
                             + s * 128 + (kb + 1) * 32 + sc4);
        }

#pragma unroll 4
        for (int k4 = 0; k4 < 32; k4++) {
            float4 w = W1s4[lane * W1P4 + k4];
#pragma unroll
            for (int u = 0; u < 4; u++) {
                float4 e = Es4[(grp * 4 + u) * 128 + kb * 32 + k4];
                acc[u] = fmaf(e.x, w.x, acc[u]);
                acc[u] = fmaf(e.y, w.y, acc[u]);
                acc[u] = fmaf(e.z, w.z, acc[u]);
                acc[u] = fmaf(e.w, w.w, acc[u]);
            }
        }
        __syncthreads();
    }

    const int j = jt * PJT + lane;
#pragma unroll
    for (int u = 0; u < 4; u++) {
        int vg = vbase + grp * 4 + u;
        if (vg < PDIM) g_P[(s * PDIM + vg) * HIDDEN + j] = acc[u];
    }
}

// ---------------------------------------------------------------------------
// Kernel B: 295 CTAs x 32 pairs, 256 threads, 2 CTAs/SM.  (identical to R9)
// ---------------------------------------------------------------------------
__global__ void __launch_bounds__(256, 2) pair_kernel(
    const float* __restrict__ b1, const float* __restrict__ W2,
    const float* __restrict__ b2, const float* __restrict__ pbeta1,
    const float* __restrict__ pbeta2, const float* __restrict__ pthr1)
{
    extern __shared__ u32 smu[];
    u32* Sh = smu;                 // [NP][SHP]
    u32* Sl = Sh + NP * SHP;       // [NP][SHP]
    u32* Wh = Sl + NP * SHP;       // [104][WHP]
    u32* Wl = Wh + WCHUNK;         // [104][WHP]

    const float beta1 = fminf(fmaxf(__ldg(pbeta1), 0.1f), 0.9f);
    const float beta2 = fminf(fmaxf(__ldg(pbeta2), 0.1f), 0.9f);
    const float thr1  = fmaxf(__ldg(pthr1), 0.1f);

    const int tid = threadIdx.x;

    // ---------------- phase 1: simulate 32 pairs x 512 h --------------------
    {
        const int q   = tid >> 3;   // pair slot 0..31
        const int sub = tid & 7;    // h-eighth
        int pp = blockIdx.x * NP + q;
        if (pp >= NPAIR) pp = 0;
        const int a = pp / PDIM;
        const int b = pp - a * PDIM;
        const float4* p1  = reinterpret_cast<const float4*>(g_P + a * HIDDEN);
        const float4* p2  = reinterpret_cast<const float4*>(g_P + (PDIM + b) * HIDDEN);
        const float4* b14 = reinterpret_cast<const float4*>(b1);

        const ull bt1 = dup_f32(beta1);
        const ull bt2 = dup_f32(beta2);
        const ull nt2 = dup_f32(-thr1);

        float4 n1 = __ldg(p1 + sub), n2 = __ldg(p2 + sub), nb = __ldg(b14 + sub);

#pragma unroll 1
        for (int o = 0; o < 16; o++) {
            const float4 v1 = n1, v2 = n2, vb = nb;
            if (o < 15) {
                const int h4n = sub + 8 * (o + 1);
                n1 = __ldg(p1 + h4n);
                n2 = __ldg(p2 + h4n);
                nb = __ldg(b14 + h4n);
            }
            ull c01 = add2(add2(pack2(v1.x, v1.y), pack2(v2.x, v2.y)),
                           pack2(vb.x, vb.y));
            ull c23 = add2(add2(pack2(v1.z, v1.w), pack2(v2.z, v2.w)),
                           pack2(vb.z, vb.w));

            ull m01 = 0, m23 = 0, S01 = 0, S23 = 0, sp01 = 0, sp23 = 0;
#pragma unroll
            for (int t = 0; t < NSTEPS; t++) {
                m01 = fma2v(sp01, nt2, fma2v(bt1, m01, c01));
                m23 = fma2v(sp23, nt2, fma2v(bt1, m23, c23));
                float a0, a1, a2, a3;
                unpack2(m01, a0, a1);
                unpack2(m23, a2, a3);
                sp01 = pack2(fsetgt(a0, thr1), fsetgt(a1, thr1));
                sp23 = pack2(fsetgt(a2, thr1), fsetgt(a3, thr1));
                S01 = fma2v(bt2, S01, sp01);
                S23 = fma2v(bt2, S23, sp23);
            }
            float s0, s1, s2, s3;
            unpack2(S01, s0, s1);
            unpack2(S23, s2, s3);
            u32 h0 = bfpack(s1, s0);
            u32 l0 = bfpack(s1 - bfhi(h0), s0 - bflo(h0));
            u32 h1 = bfpack(s3, s2);
            u32 l1 = bfpack(s3 - bfhi(h1), s2 - bflo(h1));
            const int h4 = sub + 8 * o;
            *reinterpret_cast<ull*>(Sh + q * SHP + 2 * h4) =
                (ull)h0 | ((ull)h1 << 32);
            *reinterpret_cast<ull*>(Sl + q * SHP + 2 * h4) =
                (ull)l0 | ((ull)l1 << 32);
        }
    }

    // ---------------- phase 2: tensor GEMM (3xBF16 split) -------------------
    const int warp = tid >> 5;
    const int lane = tid & 31;
    const int wm = warp & 1;
    const int wn = warp >> 1;
    const int g  = lane >> 2;
    const int t  = lane & 3;

    float acc[4][4];
#pragma unroll
    for (int j = 0; j < 4; j++)
#pragma unroll
        for (int e = 0; e < 4; e++) acc[j][e] = 0.f;

    for (int kb = 0; kb < HIDDEN / KCH; kb++) {
        if (kb > 0) __syncthreads();
        for (int idx = tid; idx < 104 * (KCH / 2); idx += 256) {
            int p  = idx >> 5;
            int kp = idx & 31;
            float2 w = make_float2(0.f, 0.f);
            if (p < PDIM)
                w = *reinterpret_cast<const float2*>(
                        W2 + p * HIDDEN + kb * KCH + 2 * kp);
            u32 h = bfpack(w.y, w.x);
            u32 l = bfpack(w.y - bfhi(h), w.x - bflo(h));
            Wh[p * WHP + kp] = h;
            Wl[p * WHP + kp] = l;
        }
        __syncthreads();

#pragma unroll
        for (int ksl = 0; ksl < KCH / 16; ksl++) {
            const int kpg = (kb * (KCH / 16) + ksl) * 8 + t;
            const int kpl = ksl * 8 + t;
            u32 ah[4], al[4];
            const int prow = wm * 16 + g;
            ah[0] = Sh[prow * SHP + kpg];
            ah[1] = Sh[(prow + 8) * SHP + kpg];
            ah[2] = Sh[prow * SHP + kpg + 4];
            ah[3] = Sh[(prow + 8) * SHP + kpg + 4];
            al[0] = Sl[prow * SHP + kpg];
            al[1] = Sl[(prow + 8) * SHP + kpg];
            al[2] = Sl[prow * SHP + kpg + 4];
            al[3] = Sl[(prow + 8) * SHP + kpg + 4];
#pragma unroll
            for (int j = 0; j < 4; j++) {
                const int nt = wn + 4 * j;
                if (nt < 13) {
                    const int nrow = nt * 8 + g;
                    u32 bh0 = Wh[nrow * WHP + kpl];
                    u32 bh1 = Wh[nrow * WHP + kpl + 4];
                    u32 bl0 = Wl[nrow * WHP + kpl];
                    u32 bl1 = Wl[nrow * WHP + kpl + 4];
                    mma_bf16(acc[j], ah, bh0, bh1);
                    mma_bf16(acc[j], al, bh0, bh1);
                    mma_bf16(acc[j], ah, bl0, bl1);
                }
            }
        }
    }

    float G = 0.0f;
#pragma unroll
    for (int t2 = 0; t2 < NSTEPS; t2++) G = __fadd_rn(__fmul_rn(beta2, G), 1.0f);

#pragma unroll
    for (int j = 0; j < 4; j++) {
        const int nt = wn + 4 * j;
        if (nt < 13) {
#pragma unroll
            for (int e = 0; e < 4; e++) {
                const int pp = blockIdx.x * NP + wm * 16 + g + (e >> 1) * 8;
                const int n = nt * 8 + 2 * t + (e & 1);
                if (pp < NPAIR && n < PDIM)
                    g_U[pp * UPITCH + n] = acc[j][e] + __ldg(b2 + n) * G;
            }
        }
    }
}

// ---------------------------------------------------------------------------
// Kernel C: out[b,:] = U[pair(b),:]. One warp per output row.
// ---------------------------------------------------------------------------
__global__ void __launch_bounds__(256) scatter_kernel(
    const int* __restrict__ x, float* __restrict__ out, int B)
{
    int warp = blockIdx.x * 8 + (threadIdx.x >> 5);
    int lane = threadIdx.x & 31;
    if (warp >= B) return;
    int x0 = __ldg(x + 2 * warp);
    int x1 = __ldg(x + 2 * warp + 1);
    const float* u = g_U + (size_t)(x0 * PDIM + x1) * UPITCH;
    float* o = out + (size_t)warp * PDIM;
#pragma unroll
    for (int j = 0; j < 3; j++) o[lane + 32 * j] = u[lane + 32 * j];
    if (lane == 0) o[96] = u[96];
}

// ---------------------------------------------------------------------------
extern "C" void kernel_launch(void* const* d_in, const int* in_sizes, int n_in,
                              void* d_out, int out_size)
{
    const int*   x     = (const int*)  d_in[0];
    const float* E     = (const float*)d_in[1];
    const float* W1    = (const float*)d_in[2];
    const float* b1    = (const float*)d_in[3];
    const float* W2    = (const float*)d_in[4];
    const float* b2    = (const float*)d_in[5];
    const float* beta1 = (const float*)d_in[6];
    const float* beta2 = (const float*)d_in[7];
    const float* thr1  = (const float*)d_in[8];
    // thr2 unused in forward (lif2 reset='none'; output is mem2).

    const int B = in_sizes[0] / 2;

    const int psmemB = (PVT * (HIDDEN / 4) + PJT * W1P4) * (int)sizeof(float4); // 49664
    cudaFuncSetAttribute(precompute_kernel,
                         cudaFuncAttributeMaxDynamicSharedMemorySize, psmemB);

    const int smemB = (2 * NP * SHP + 2 * WCHUNK) * (int)sizeof(u32); // 96512 B
    cudaFuncSetAttribute(pair_kernel, cudaFuncAttributeMaxDynamicSharedMemorySize, smemB);

    precompute_kernel<<<dim3(16, 7, 2), 128, psmemB>>>(E, W1);
    pair_kernel<<<(NPAIR + NP - 1) / NP, 256, smemB>>>(b1, W2, b2, beta1, beta2, thr1);
    scatter_kernel<<<(B + 7) / 8, 256>>>(x, (float*)d_out, B);
}

// round 11
// speedup vs baseline: 1.0378x; 1.0378x over previous
#include <cuda_runtime.h>
#include <cstdint>

// GrokkingSNN: B=32768, hidden=512, p=97, 15 steps.
//   cur1[b,j] = P1[x0,j] + P2[x1,j] + b1[j], P = E @ W1half.T
//   9409 distinct pairs -> simulate per pair; mem2 = S @ W2.T + b2*G.
// R11: precompute staged entirely via cp.async (48 LDGSTS/thread, one sync)
//      to break the MLP/DRAM-latency wall; FMA chains bit-identical to R10.
//      Pair + scatter kernels identical to R9/R10.

#define HIDDEN 512
#define PDIM 97
#define NPAIR (PDIM * PDIM)   // 9409
#define NSTEPS 15
#define UPITCH 104

#define NP 32       // pairs per CTA (pair kernel)
#define SHP 260     // S bf16x2 pitch (u32/row)
#define WHP 36      // W2 bf16x2 chunk pitch (u32/row)
#define KCH 64      // K per W2 chunk
#define WCHUNK (104 * WHP)

// precompute tiling
#define PJT 32      // j per block
#define PVT 16      // v per block (4 per thread)
#define W1PIT 129   // W1 tile pitch in float4 (odd mod 8 -> conflict-free LDS.128)

__device__ float g_P[2 * PDIM * HIDDEN];
__device__ float g_U[NPAIR * UPITCH];

typedef unsigned long long ull;
typedef unsigned int u32;

__device__ __forceinline__ ull fma2v(ull a, ull b, ull c) {
    ull d; asm("fma.rn.f32x2 %0, %1, %2, %3;" : "=l"(d) : "l"(a), "l"(b), "l"(c));
    return d;
}
__device__ __forceinline__ ull add2(ull a, ull b) {
    ull d; asm("add.rn.f32x2 %0, %1, %2;" : "=l"(d) : "l"(a), "l"(b));
    return d;
}
__device__ __forceinline__ ull pack2(float lo, float hi) {
    ull u; asm("mov.b64 %0, {%1, %2};" : "=l"(u) : "f"(lo), "f"(hi));
    return u;
}
__device__ __forceinline__ ull dup_f32(float w) {
    ull u; asm("mov.b64 %0, {%1, %1};" : "=l"(u) : "f"(w));
    return u;
}
__device__ __forceinline__ void unpack2(ull v, float& lo, float& hi) {
    asm("mov.b64 {%0, %1}, %2;" : "=f"(lo), "=f"(hi) : "l"(v));
}
__device__ __forceinline__ float fsetgt(float a, float b) {
    float d; asm("set.gt.f32.f32 %0, %1, %2;" : "=f"(d) : "f"(a), "f"(b));
    return d;
}
__device__ __forceinline__ u32 bfpack(float hif, float lof) {
    u32 d; asm("cvt.rn.bf16x2.f32 %0, %1, %2;" : "=r"(d) : "f"(hif), "f"(lof));
    return d;
}
__device__ __forceinline__ float bflo(u32 d) { return __uint_as_float(d << 16); }
__device__ __forceinline__ float bfhi(u32 d) { return __uint_as_float(d & 0xFFFF0000u); }

__device__ __forceinline__ void mma_bf16(float* c, const u32* a, u32 b0, u32 b1) {
    asm("mma.sync.aligned.m16n8k16.row.col.f32.bf16.bf16.f32 "
        "{%0,%1,%2,%3}, {%4,%5,%6,%7}, {%8,%9}, {%0,%1,%2,%3};"
        : "+f"(c[0]), "+f"(c[1]), "+f"(c[2]), "+f"(c[3])
        : "r"(a[0]), "r"(a[1]), "r"(a[2]), "r"(a[3]), "r"(b0), "r"(b1));
}

__device__ __forceinline__ void cpa16(u32 smem_addr, const void* gptr) {
    asm volatile("cp.async.cg.shared.global [%0], [%1], 16;"
                 :: "r"(smem_addr), "l"(gptr));
}

// ---------------------------------------------------------------------------
// Kernel A: P[s][v][j] = sum_k E[v][k] * W1[j][s*512+k]
// grid (16 jt, 7 vt of 16 v, 2 s) = 224 CTAs, 128 threads, 2 CTAs/SM.
// Entire E tile + W1 tile staged via cp.async (48 LDGSTS/thread), one sync,
// then one straight 128-iter FMA loop. Chains bit-identical to R10.
// ---------------------------------------------------------------------------
__global__ void __launch_bounds__(128, 2) precompute_kernel(
    const float* __restrict__ E, const float* __restrict__ W1)
{
    extern __shared__ float4 psm[];
    float4* Es4  = psm;                        // [PVT][128]
    float4* W1s4 = psm + PVT * (HIDDEN / 4);   // [PJT][W1PIT]

    const int jt = blockIdx.x, vt = blockIdx.y, s = blockIdx.z;
    const int tid  = threadIdx.x;
    const int lane = tid & 31;    // j within tile
    const int grp  = tid >> 5;    // warp -> 4 v rows
    const int vbase = vt * PVT;

    const float4* E4  = reinterpret_cast<const float4*>(E);
    const float4* W14 = reinterpret_cast<const float4*>(W1);  // row stride 256

    const u32 sE = (u32)__cvta_generic_to_shared(Es4);
    const u32 sW = (u32)__cvta_generic_to_shared(W1s4);

    // E tile: 16 rows x 128 f4 (rows past 96 clamp -> garbage, never stored)
#pragma unroll
    for (int r = 0; r < PVT; r++) {
        int idx = tid + 128 * r;
        int vv = idx >> 7;
        int c4 = idx & 127;
        int v  = vbase + vv;
        int vl = (v < PDIM) ? v : (PDIM - 1);
        cpa16(sE + (u32)(vv * 128 + c4) * 16, E4 + (size_t)vl * 128 + c4);
    }
    // W1 tile: 32 rows x 128 f4
#pragma unroll
    for (int r = 0; r < 32; r++) {
        int idx = tid + 128 * r;
        int row = idx >> 7;
        int c4  = idx & 127;
        cpa16(sW + (u32)(row * W1PIT + c4) * 16,
              W14 + (size_t)(jt * PJT + row) * 256 + s * 128 + c4);
    }
    asm volatile("cp.async.commit_group;");
    asm volatile("cp.async.wait_group 0;");
    __syncthreads();

    float acc[4];
#pragma unroll
    for (int u = 0; u < 4; u++) acc[u] = 0.f;

#pragma unroll 4
    for (int k4 = 0; k4 < HIDDEN / 4; k4++) {
        float4 w = W1s4[lane * W1PIT + k4];
#pragma unroll
        for (int u = 0; u < 4; u++) {
            float4 e = Es4[(grp * 4 + u) * 128 + k4];
            acc[u] = fmaf(e.x, w.x, acc[u]);
            acc[u] = fmaf(e.y, w.y, acc[u]);
            acc[u] = fmaf(e.z, w.z, acc[u]);
            acc[u] = fmaf(e.w, w.w, acc[u]);
        }
    }

    const int j = jt * PJT + lane;
#pragma unroll
    for (int u = 0; u < 4; u++) {
        int vg = vbase + grp * 4 + u;
        if (vg < PDIM) g_P[(s * PDIM + vg) * HIDDEN + j] = acc[u];
    }
}

// ---------------------------------------------------------------------------
// Kernel B: 295 CTAs x 32 pairs, 256 threads, 2 CTAs/SM.  (identical to R9)
// ---------------------------------------------------------------------------
__global__ void __launch_bounds__(256, 2) pair_kernel(
    const float* __restrict__ b1, const float* __restrict__ W2,
    const float* __restrict__ b2, const float* __restrict__ pbeta1,
    const float* __restrict__ pbeta2, const float* __restrict__ pthr1)
{
    extern __shared__ u32 smu[];
    u32* Sh = smu;                 // [NP][SHP]
    u32* Sl = Sh + NP * SHP;       // [NP][SHP]
    u32* Wh = Sl + NP * SHP;       // [104][WHP]
    u32* Wl = Wh + WCHUNK;         // [104][WHP]

    const float beta1 = fminf(fmaxf(__ldg(pbeta1), 0.1f), 0.9f);
    const float beta2 = fminf(fmaxf(__ldg(pbeta2), 0.1f), 0.9f);
    const float thr1  = fmaxf(__ldg(pthr1), 0.1f);

    const int tid = threadIdx.x;

    // ---------------- phase 1: simulate 32 pairs x 512 h --------------------
    {
        const int q   = tid >> 3;   // pair slot 0..31
        const int sub = tid & 7;    // h-eighth
        int pp = blockIdx.x * NP + q;
        if (pp >= NPAIR) pp = 0;
        const int a = pp / PDIM;
        const int b = pp - a * PDIM;
        const float4* p1  = reinterpret_cast<const float4*>(g_P + a * HIDDEN);
        const float4* p2  = reinterpret_cast<const float4*>(g_P + (PDIM + b) * HIDDEN);
        const float4* b14 = reinterpret_cast<const float4*>(b1);

        const ull bt1 = dup_f32(beta1);
        const ull bt2 = dup_f32(beta2);
        const ull nt2 = dup_f32(-thr1);

        float4 n1 = __ldg(p1 + sub), n2 = __ldg(p2 + sub), nb = __ldg(b14 + sub);

#pragma unroll 1
        for (int o = 0; o < 16; o++) {
            const float4 v1 = n1, v2 = n2, vb = nb;
            if (o < 15) {
                const int h4n = sub + 8 * (o + 1);
                n1 = __ldg(p1 + h4n);
                n2 = __ldg(p2 + h4n);
                nb = __ldg(b14 + h4n);
            }
            ull c01 = add2(add2(pack2(v1.x, v1.y), pack2(v2.x, v2.y)),
                           pack2(vb.x, vb.y));
            ull c23 = add2(add2(pack2(v1.z, v1.w), pack2(v2.z, v2.w)),
                           pack2(vb.z, vb.w));

            ull m01 = 0, m23 = 0, S01 = 0, S23 = 0, sp01 = 0, sp23 = 0;
#pragma unroll
            for (int t = 0; t < NSTEPS; t++) {
                m01 = fma2v(sp01, nt2, fma2v(bt1, m01, c01));
                m23 = fma2v(sp23, nt2, fma2v(bt1, m23, c23));
                float a0, a1, a2, a3;
                unpack2(m01, a0, a1);
                unpack2(m23, a2, a3);
                sp01 = pack2(fsetgt(a0, thr1), fsetgt(a1, thr1));
                sp23 = pack2(fsetgt(a2, thr1), fsetgt(a3, thr1));
                S01 = fma2v(bt2, S01, sp01);
                S23 = fma2v(bt2, S23, sp23);
            }
            float s0, s1, s2, s3;
            unpack2(S01, s0, s1);
            unpack2(S23, s2, s3);
            u32 h0 = bfpack(s1, s0);
            u32 l0 = bfpack(s1 - bfhi(h0), s0 - bflo(h0));
            u32 h1 = bfpack(s3, s2);
            u32 l1 = bfpack(s3 - bfhi(h1), s2 - bflo(h1));
            const int h4 = sub + 8 * o;
            *reinterpret_cast<ull*>(Sh + q * SHP + 2 * h4) =
                (ull)h0 | ((ull)h1 << 32);
            *reinterpret_cast<ull*>(Sl + q * SHP + 2 * h4) =
                (ull)l0 | ((ull)l1 << 32);
        }
    }

    // ---------------- phase 2: tensor GEMM (3xBF16 split) -------------------
    const int warp = tid >> 5;
    const int lane = tid & 31;
    const int wm = warp & 1;
    const int wn = warp >> 1;
    const int g  = lane >> 2;
    const int t  = lane & 3;

    float acc[4][4];
#pragma unroll
    for (int j = 0; j < 4; j++)
#pragma unroll
        for (int e = 0; e < 4; e++) acc[j][e] = 0.f;

    for (int kb = 0; kb < HIDDEN / KCH; kb++) {
        if (kb > 0) __syncthreads();
        for (int idx = tid; idx < 104 * (KCH / 2); idx += 256) {
            int p  = idx >> 5;
            int kp = idx & 31;
            float2 w = make_float2(0.f, 0.f);
            if (p < PDIM)
                w = *reinterpret_cast<const float2*>(
                        W2 + p * HIDDEN + kb * KCH + 2 * kp);
            u32 h = bfpack(w.y, w.x);
            u32 l = bfpack(w.y - bfhi(h), w.x - bflo(h));
            Wh[p * WHP + kp] = h;
            Wl[p * WHP + kp] = l;
        }
        __syncthreads();

#pragma unroll
        for (int ksl = 0; ksl < KCH / 16; ksl++) {
            const int kpg = (kb * (KCH / 16) + ksl) * 8 + t;
            const int kpl = ksl * 8 + t;
            u32 ah[4], al[4];
            const int prow = wm * 16 + g;
            ah[0] = Sh[prow * SHP + kpg];
            ah[1] = Sh[(prow + 8) * SHP + kpg];
            ah[2] = Sh[prow * SHP + kpg + 4];
            ah[3] = Sh[(prow + 8) * SHP + kpg + 4];
            al[0] = Sl[prow * SHP + kpg];
            al[1] = Sl[(prow + 8) * SHP + kpg];
            al[2] = Sl[prow * SHP + kpg + 4];
            al[3] = Sl[(prow + 8) * SHP + kpg + 4];
#pragma unroll
            for (int j = 0; j < 4; j++) {
                const int nt = wn + 4 * j;
                if (nt < 13) {
                    const int nrow = nt * 8 + g;
                    u32 bh0 = Wh[nrow * WHP + kpl];
                    u32 bh1 = Wh[nrow * WHP + kpl + 4];
                    u32 bl0 = Wl[nrow * WHP + kpl];
                    u32 bl1 = Wl[nrow * WHP + kpl + 4];
                    mma_bf16(acc[j], ah, bh0, bh1);
                    mma_bf16(acc[j], al, bh0, bh1);
                    mma_bf16(acc[j], ah, bl0, bl1);
                }
            }
        }
    }

    float G = 0.0f;
#pragma unroll
    for (int t2 = 0; t2 < NSTEPS; t2++) G = __fadd_rn(__fmul_rn(beta2, G), 1.0f);

#pragma unroll
    for (int j = 0; j < 4; j++) {
        const int nt = wn + 4 * j;
        if (nt < 13) {
#pragma unroll
            for (int e = 0; e < 4; e++) {
                const int pp = blockIdx.x * NP + wm * 16 + g + (e >> 1) * 8;
                const int n = nt * 8 + 2 * t + (e & 1);
                if (pp < NPAIR && n < PDIM)
                    g_U[pp * UPITCH + n] = acc[j][e] + __ldg(b2 + n) * G;
            }
        }
    }
}

// ---------------------------------------------------------------------------
// Kernel C: out[b,:] = U[pair(b),:]. One warp per output row.
// ---------------------------------------------------------------------------
__global__ void __launch_bounds__(256) scatter_kernel(
    const int* __restrict__ x, float* __restrict__ out, int B)
{
    int warp = blockIdx.x * 8 + (threadIdx.x >> 5);
    int lane = threadIdx.x & 31;
    if (warp >= B) return;
    int x0 = __ldg(x + 2 * warp);
    int x1 = __ldg(x + 2 * warp + 1);
    const float* u = g_U + (size_t)(x0 * PDIM + x1) * UPITCH;
    float* o = out + (size_t)warp * PDIM;
#pragma unroll
    for (int j = 0; j < 3; j++) o[lane + 32 * j] = u[lane + 32 * j];
    if (lane == 0) o[96] = u[96];
}

// ---------------------------------------------------------------------------
extern "C" void kernel_launch(void* const* d_in, const int* in_sizes, int n_in,
                              void* d_out, int out_size)
{
    const int*   x     = (const int*)  d_in[0];
    const float* E     = (const float*)d_in[1];
    const float* W1    = (const float*)d_in[2];
    const float* b1    = (const float*)d_in[3];
    const float* W2    = (const float*)d_in[4];
    const float* b2    = (const float*)d_in[5];
    const float* beta1 = (const float*)d_in[6];
    const float* beta2 = (const float*)d_in[7];
    const float* thr1  = (const float*)d_in[8];
    // thr2 unused in forward (lif2 reset='none'; output is mem2).

    const int B = in_sizes[0] / 2;

    const int psmemB = (PVT * (HIDDEN / 4) + PJT * W1PIT) * (int)sizeof(float4); // 98816
    cudaFuncSetAttribute(precompute_kernel,
                         cudaFuncAttributeMaxDynamicSharedMemorySize, psmemB);

    const int smemB = (2 * NP * SHP + 2 * WCHUNK) * (int)sizeof(u32); // 96512 B
    cudaFuncSetAttribute(pair_kernel, cudaFuncAttributeMaxDynamicSharedMemorySize, smemB);

    precompute_kernel<<<dim3(16, 7, 2), 128, psmemB>>>(E, W1);
    pair_kernel<<<(NPAIR + NP - 1) / NP, 256, smemB>>>(b1, W2, b2, beta1, beta2, thr1);
    scatter_kernel<<<(B + 7) / 8, 256>>>(x, (float*)d_out, B);
}